// round 3
// baseline (speedup 1.0000x reference)
#include <cuda_runtime.h>
#include <math.h>

#define HW_   96
#define CIN_  64
#define COUT_ 64
#define B_    4
#define T_    8
#define PLANE (HW_*HW_)
#define TILE  32
#define CICH  8
#define HALO  34
#define SPITCH 36     // even => aligned float2 rows
#define NTHR  128

// Scratch state (no runtime allocation allowed)
__device__ float g_h [B_*COUT_*PLANE];
__device__ float g_rh[B_*COUT_*PLANE];
__device__ float g_z [B_*COUT_*PLANE];

typedef unsigned long long u64;

__device__ __forceinline__ u64 pack2(float lo, float hi) {
    u64 r; asm("mov.b64 %0, {%1, %2};" : "=l"(r) : "f"(lo), "f"(hi)); return r;
}
__device__ __forceinline__ void unpack2(u64 v, float &lo, float &hi) {
    asm("mov.b64 {%0, %1}, %2;" : "=f"(lo), "=f"(hi) : "l"(v));
}
// packed fp32x2 FMA: d = a*b + d   (Blackwell FFMA2)
__device__ __forceinline__ void fma2(u64 &d, u64 a, u64 b) {
    asm("fma.rn.f32x2 %0, %1, %2, %0;" : "+l"(d) : "l"(a), "l"(b));
}

// 32x32 output tile of 3x3 SAME conv over concat([srcA(64ch), srcB(64ch)]),
// COBT output channels from co_base. acc = packed pixel-pairs, 4 rows x COBT.
template<int COBT>
__device__ __forceinline__ void conv_tile(
    const float* __restrict__ srcA,
    const float* __restrict__ srcB,
    const float* __restrict__ wts,    // [64][128][3][3]
    const float* __restrict__ bias,
    int co_base, int tile_x, int tile_y, int tid,
    u64 acc[4][COBT])
{
    __shared__ float s_in[CICH][HALO][SPITCH];
    __shared__ __align__(16) u64 s_w[CICH][COBT][10];

    const int tx   = tid & 15;      // x pixel-pair
    const int ty   = tid >> 4;      // 4-row group
    const int wid  = tid >> 5;
    const int lane = tid & 31;

    #pragma unroll
    for (int co = 0; co < COBT; co++) {
        float bv = bias[co_base + co];
        u64 bp = pack2(bv, bv);
        #pragma unroll
        for (int pr = 0; pr < 4; pr++) acc[pr][co] = bp;
    }

    const int base_y = tile_y * TILE - 1;
    const int base_x = tile_x * TILE - 1;
    const int lx = tx * 2;
    const int ly = ty * 4;

    for (int src = 0; src < 2; src++) {
        const float* sp = src ? srcB : srcA;
        for (int cc = 0; cc < CIN_ / CICH; cc++) {
            // ---- coalesced halo fill: warp w handles channels 2w, 2w+1 ----
            #pragma unroll
            for (int i = 0; i < 2; i++) {
                int ci = wid * 2 + i;
                const float* cp = sp + (size_t)(cc * CICH + ci) * PLANE;
                for (int r = 0; r < HALO; r++) {
                    int gy = base_y + r;
                    bool rowok = (unsigned)gy < HW_;
                    int gx0 = base_x + lane;
                    float v0 = 0.0f;
                    if (rowok && (unsigned)gx0 < HW_) v0 = cp[gy * HW_ + gx0];
                    s_in[ci][r][lane] = v0;
                    if (lane < 2) {
                        int gx1 = gx0 + 32;
                        float v1 = 0.0f;
                        if (rowok && (unsigned)gx1 < HW_) v1 = cp[gy * HW_ + gx1];
                        s_in[ci][r][lane + 32] = v1;
                    }
                }
            }
            // ---- weights: one thread per (ci,co), duplicated packed halves ----
            if (tid < CICH * COBT) {
                int ci = tid / COBT;
                int co = tid - ci * COBT;
                const float* wp = wts +
                    ((size_t)(co_base + co) * (CIN_ + COUT_) + src * CIN_ + cc * CICH + ci) * 9;
                #pragma unroll
                for (int k = 0; k < 9; k++) {
                    float wv = wp[k];
                    s_w[ci][co][k] = pack2(wv, wv);
                }
            }
            __syncthreads();

            #pragma unroll 2
            for (int ci = 0; ci < CICH; ci++) {
                const float* ip = &s_in[ci][ly][lx];
                u64 p[6][3];
                #pragma unroll
                for (int r = 0; r < 6; r++) {
                    float2 q0 = *(const float2*)(ip + r * SPITCH);
                    float2 q1 = *(const float2*)(ip + r * SPITCH + 2);
                    p[r][0] = pack2(q0.x, q0.y);
                    p[r][1] = pack2(q0.y, q1.x);
                    p[r][2] = pack2(q1.x, q1.y);
                }
                const u64* wrow = &s_w[ci][0][0];
                #pragma unroll
                for (int co = 0; co < COBT; co++) {
                    ulonglong2 t0 = *(const ulonglong2*)(wrow + co * 10 + 0);
                    ulonglong2 t1 = *(const ulonglong2*)(wrow + co * 10 + 2);
                    ulonglong2 t2 = *(const ulonglong2*)(wrow + co * 10 + 4);
                    ulonglong2 t3 = *(const ulonglong2*)(wrow + co * 10 + 6);
                    u64 w8 = wrow[co * 10 + 8];
                    u64 wv[9] = {t0.x, t0.y, t1.x, t1.y, t2.x, t2.y, t3.x, t3.y, w8};
                    // k outer, pr inner: consecutive FMAs hit different accumulators
                    #pragma unroll
                    for (int k = 0; k < 9; k++) {
                        int ky = k / 3, kx = k - ky * 3;
                        #pragma unroll
                        for (int pr = 0; pr < 4; pr++)
                            fma2(acc[pr][co], wv[k], p[pr + ky][kx]);
                    }
                }
            }
            __syncthreads();
        }
    }
}

__device__ __forceinline__ float sigmoidf_(float v) {
    return 1.0f / (1.0f + expf(-v));
}

// grid: (3, 3, 64)  bz: b = bz>>4, gate = (bz>>3)&1, cg = bz&7  (COB=8)
__global__ void __launch_bounds__(NTHR, 4) gates_kernel(
    const float* __restrict__ x,
    const float* __restrict__ w_r, const float* __restrict__ b_r,
    const float* __restrict__ w_z, const float* __restrict__ b_z,
    int t)
{
    const int bz   = blockIdx.z;
    const int b    = bz >> 4;
    const int gate = (bz >> 3) & 1;
    const int cg   = bz & 7;

    const float* srcA = x + (size_t)(b * T_ + t) * CIN_ * PLANE;
    const float* srcB = g_h + (size_t)b * COUT_ * PLANE;
    const float* wts  = gate ? w_z : w_r;
    const float* bias = gate ? b_z : b_r;

    u64 acc[4][8];
    const int tid = threadIdx.x;
    conv_tile<8>(srcA, srcB, wts, bias, cg * 8, blockIdx.x, blockIdx.y, tid, acc);

    const int tx = tid & 15, ty = tid >> 4;
    const int gy0 = blockIdx.y * TILE + ty * 4;
    const int gx  = blockIdx.x * TILE + tx * 2;
    #pragma unroll
    for (int pr = 0; pr < 4; pr++) {
        int gy = gy0 + pr;
        #pragma unroll
        for (int co = 0; co < 8; co++) {
            float v0, v1; unpack2(acc[pr][co], v0, v1);
            int cglob = cg * 8 + co;
            size_t idx = (size_t)(b * COUT_ + cglob) * PLANE + gy * HW_ + gx;
            float s0 = sigmoidf_(v0);
            float s1 = sigmoidf_(v1);
            if (gate == 0) {
                g_rh[idx]     = s0 * g_h[idx];
                g_rh[idx + 1] = s1 * g_h[idx + 1];
            } else {
                g_z[idx]     = s0;
                g_z[idx + 1] = s1;
            }
        }
    }
}

// grid: (3, 3, 64)  bz: b = bz>>4, cg = bz&15  (COB=4)
__global__ void __launch_bounds__(NTHR, 4) update_kernel(
    const float* __restrict__ x,
    const float* __restrict__ w_h, const float* __restrict__ b_h,
    float* __restrict__ out, int t)
{
    const int bz = blockIdx.z;
    const int b  = bz >> 4;
    const int cg = bz & 15;

    const float* srcA = x + (size_t)(b * T_ + t) * CIN_ * PLANE;
    const float* srcB = g_rh + (size_t)b * COUT_ * PLANE;

    u64 acc[4][4];
    const int tid = threadIdx.x;
    conv_tile<4>(srcA, srcB, w_h, b_h, cg * 4, blockIdx.x, blockIdx.y, tid, acc);

    const int tx = tid & 15, ty = tid >> 4;
    const int gy0 = blockIdx.y * TILE + ty * 4;
    const int gx  = blockIdx.x * TILE + tx * 2;
    #pragma unroll
    for (int pr = 0; pr < 4; pr++) {
        int gy = gy0 + pr;
        #pragma unroll
        for (int co = 0; co < 4; co++) {
            float v0, v1; unpack2(acc[pr][co], v0, v1);
            int cglob = cg * 4 + co;
            size_t idx  = (size_t)(b * COUT_ + cglob) * PLANE + gy * HW_ + gx;
            size_t oidx = (size_t)((b * T_ + t) * COUT_ + cglob) * PLANE + gy * HW_ + gx;
            float ht0 = tanhf(v0), ht1 = tanhf(v1);
            float z0 = g_z[idx],     z1 = g_z[idx + 1];
            float h0 = g_h[idx],     h1 = g_h[idx + 1];
            float hn0 = h0 + z0 * (ht0 - h0);
            float hn1 = h1 + z1 * (ht1 - h1);
            g_h[idx]     = hn0;  g_h[idx + 1] = hn1;
            out[oidx]    = hn0;  out[oidx + 1] = hn1;
        }
    }
}

__global__ void zero_h_kernel() {
    int i = blockIdx.x * 256 + threadIdx.x;
    if (i < B_ * COUT_ * PLANE) g_h[i] = 0.0f;
}

extern "C" void kernel_launch(void* const* d_in, const int* in_sizes, int n_in,
                              void* d_out, int out_size)
{
    const float* x   = (const float*)d_in[0];
    const float* w_r = (const float*)d_in[1];
    const float* b_r = (const float*)d_in[2];
    const float* w_z = (const float*)d_in[3];
    const float* b_z = (const float*)d_in[4];
    const float* w_h = (const float*)d_in[5];
    const float* b_h = (const float*)d_in[6];
    float* out = (float*)d_out;

    zero_h_kernel<<<(B_ * COUT_ * PLANE + 255) / 256, 256>>>();

    dim3 gGrid(HW_ / TILE, HW_ / TILE, B_ * 2 * (COUT_ / 8));   // 3,3,64
    dim3 uGrid(HW_ / TILE, HW_ / TILE, B_ * (COUT_ / 4));       // 3,3,64
    for (int t = 0; t < T_; t++) {
        gates_kernel<<<gGrid, NTHR>>>(x, w_r, b_r, w_z, b_z, t);
        update_kernel<<<uGrid, NTHR>>>(x, w_h, b_h, out, t);
    }
}

// round 7
// speedup vs baseline: 2.0074x; 2.0074x over previous
#include <cuda_runtime.h>
#include <math.h>
#include <stdint.h>

#define HW_   96
#define CIN_  64
#define COUT_ 64
#define B_    4
#define T_    8
#define PLANE (HW_*HW_)
#define TILE  32
#define CICH  8
#define NCHUNK 16          // 2 sources * (64/8)
#define HALO  34
#define SPITCH 36          // even -> float2-aligned rows
#define NTHR  128

// Scratch state (no runtime allocation allowed)
__device__ float g_h [B_*COUT_*PLANE];
__device__ float g_rh[B_*COUT_*PLANE];
__device__ float g_z [B_*COUT_*PLANE];

typedef unsigned long long u64;

__device__ __forceinline__ u64 pack2(float lo, float hi) {
    u64 r; asm("mov.b64 %0, {%1, %2};" : "=l"(r) : "f"(lo), "f"(hi)); return r;
}
__device__ __forceinline__ void unpack2(u64 v, float &lo, float &hi) {
    asm("mov.b64 {%0, %1}, %2;" : "=f"(lo), "=f"(hi) : "l"(v));
}
// packed fp32x2 FMA: d = a*b + d
__device__ __forceinline__ void fma2(u64 &d, u64 a, u64 b) {
    asm("fma.rn.f32x2 %0, %1, %2, %0;" : "+l"(d) : "l"(a), "l"(b));
}
__device__ __forceinline__ uint32_t s2u(const void* p) {
    return (uint32_t)__cvta_generic_to_shared(p);
}
__device__ __forceinline__ void cp4(uint32_t smem, const float* g, bool v) {
    asm volatile("cp.async.ca.shared.global [%0], [%1], 4, %2;"
                 :: "r"(smem), "l"(g), "r"(v ? 4u : 0u));
}
#define CP_COMMIT() asm volatile("cp.async.commit_group;" ::: "memory")
#define CP_WAIT0()  asm volatile("cp.async.wait_group 0;"  ::: "memory")

template<int COBT> struct SM {
    float in[2][CICH][HALO][SPITCH];          // double-buffered input chunks
    u64   w [2][CICH][COBT][10];              // double-buffered packed weights
};

// ---------------------------------------------------------------------------
// 32x32 output tile of 3x3 SAME conv over concat([srcA(64ch), srcB(64ch)]).
// COBT output channels from co_base. acc = packed pixel pairs, 4 rows x COBT.
// Double-buffered cp.async pipeline over 16 channel-chunks.
// ---------------------------------------------------------------------------
template<int COBT>
__device__ __forceinline__ void conv_tile(
    const float* __restrict__ srcA,
    const float* __restrict__ srcB,
    const float* __restrict__ wts,    // [COUT][128][3][3]
    const float* __restrict__ bias,
    int co_base, int tile_x, int tile_y, int tid,
    u64 acc[4][COBT])
{
    extern __shared__ char dynsmem[];
    SM<COBT>* sm = reinterpret_cast<SM<COBT>*>(dynsmem);

    const int tx   = tid & 15;
    const int ty   = tid >> 4;
    const int wid  = tid >> 5;
    const int lane = tid & 31;
    const int lx = tx * 2;
    const int ly = ty * 4;
    const int base_y = tile_y * TILE - 1;
    const int base_x = tile_x * TILE - 1;

    // weight-prefetch role: thread -> (co, ci); active if co < COBT
    const int wco = tid >> 3;
    const int wci = tid & 7;
    const bool wact = (wco < COBT);

    #pragma unroll
    for (int co = 0; co < COBT; co++) {
        float bv = bias[co_base + co];
        u64 bp = pack2(bv, bv);
        #pragma unroll
        for (int pr = 0; pr < 4; pr++) acc[pr][co] = bp;
    }

    // ---- helpers as lambdas ----
    auto loadw = [&](int c, float wreg[9]) {
        int src = c >> 3, cc = c & 7;
        const float* wp = wts +
            ((size_t)(co_base + wco) * (CIN_ + COUT_) + src * CIN_ + cc * CICH + wci) * 9;
        #pragma unroll
        for (int k = 0; k < 9; k++) wreg[k] = wp[k];
    };
    auto stsw = [&](int c, const float wreg[9]) {
        int buf = c & 1;
        #pragma unroll
        for (int k = 0; k < 9; k++)
            sm->w[buf][wci][wco][k] = pack2(wreg[k], wreg[k]);
    };
    auto cpin = [&](int c) {
        int buf = c & 1;
        int src = c >> 3, cc = c & 7;
        const float* sp = src ? srcB : srcA;
        #pragma unroll
        for (int i = 0; i < 2; i++) {
            int ci = wid * 2 + i;
            const float* chp = sp + (size_t)(cc * CICH + ci) * PLANE;
            for (int r = 0; r < HALO; r++) {
                int gy = base_y + r;
                bool rok = (unsigned)gy < HW_;
                int gx0 = base_x + lane;
                cp4(s2u(&sm->in[buf][ci][r][lane]), chp + gy * HW_ + gx0,
                    rok && (unsigned)gx0 < HW_);
                if (lane < 2) {
                    int gx1 = gx0 + 32;
                    cp4(s2u(&sm->in[buf][ci][r][lane + 32]), chp + gy * HW_ + gx1,
                        rok && (unsigned)gx1 < HW_);
                }
            }
        }
    };

    // ---- prologue: stage chunk 0 ----
    float wreg[9];
    if (wact) loadw(0, wreg);
    cpin(0);
    CP_COMMIT();
    if (wact) stsw(0, wreg);

    // ---- pipelined mainloop ----
    for (int c = 0; c < NCHUNK; c++) {
        const int buf = c & 1;
        const bool more = (c + 1) < NCHUNK;
        if (more && wact) loadw(c + 1, wreg);     // gmem->reg, no smem hazard
        CP_WAIT0();                               // chunk c's inputs landed
        __syncthreads();                          // all warps done with buf^1
        if (more) {
            cpin(c + 1);                          // fill buf^1 (async)
            CP_COMMIT();
            if (wact) stsw(c + 1, wreg);          // drained by next sync
        }
        // ---- compute chunk c from sm[buf] ----
        #pragma unroll
        for (int ci = 0; ci < CICH; ci++) {
            const float* ip = &sm->in[buf][ci][ly][lx];
            u64 p[6][3];
            #pragma unroll
            for (int r = 0; r < 6; r++) {
                float2 q0 = *(const float2*)(ip + r * SPITCH);
                float2 q1 = *(const float2*)(ip + r * SPITCH + 2);
                p[r][0] = pack2(q0.x, q0.y);
                p[r][1] = pack2(q0.y, q1.x);
                p[r][2] = pack2(q1.x, q1.y);
            }
            const u64* wrow = &sm->w[buf][ci][0][0];
            #pragma unroll
            for (int co = 0; co < COBT; co++) {
                ulonglong2 t0 = *(const ulonglong2*)(wrow + co * 10 + 0);
                ulonglong2 t1 = *(const ulonglong2*)(wrow + co * 10 + 2);
                ulonglong2 t2 = *(const ulonglong2*)(wrow + co * 10 + 4);
                ulonglong2 t3 = *(const ulonglong2*)(wrow + co * 10 + 6);
                u64 w8 = wrow[co * 10 + 8];
                u64 wv[9] = {t0.x, t0.y, t1.x, t1.y, t2.x, t2.y, t3.x, t3.y, w8};
                #pragma unroll
                for (int k = 0; k < 9; k++) {
                    int ky = k / 3, kx = k - ky * 3;
                    #pragma unroll
                    for (int pr = 0; pr < 4; pr++)
                        fma2(acc[pr][co], wv[k], p[pr + ky][kx]);
                }
            }
        }
    }
}

__device__ __forceinline__ float sigmoidf_(float v) {
    return 1.0f / (1.0f + expf(-v));
}

// grid: (3, 3, 32)  bz: b = bz>>3, gate = (bz>>2)&1, cg = bz&3  (COB=16)
__global__ void __launch_bounds__(NTHR) gates_kernel(
    const float* __restrict__ x,
    const float* __restrict__ w_r, const float* __restrict__ b_r,
    const float* __restrict__ w_z, const float* __restrict__ b_z,
    int t)
{
    const int bz   = blockIdx.z;
    const int b    = bz >> 3;
    const int gate = (bz >> 2) & 1;
    const int cg   = bz & 3;

    const float* srcA = x + (size_t)(b * T_ + t) * CIN_ * PLANE;
    const float* srcB = g_h + (size_t)b * COUT_ * PLANE;
    const float* wts  = gate ? w_z : w_r;
    const float* bias = gate ? b_z : b_r;

    u64 acc[4][16];
    const int tid = threadIdx.x;
    conv_tile<16>(srcA, srcB, wts, bias, cg * 16, blockIdx.x, blockIdx.y, tid, acc);

    const int tx = tid & 15, ty = tid >> 4;
    const int gy0 = blockIdx.y * TILE + ty * 4;
    const int gx  = blockIdx.x * TILE + tx * 2;
    #pragma unroll
    for (int pr = 0; pr < 4; pr++) {
        int gy = gy0 + pr;
        #pragma unroll
        for (int co = 0; co < 16; co++) {
            float v0, v1; unpack2(acc[pr][co], v0, v1);
            int cglob = cg * 16 + co;
            size_t idx = (size_t)(b * COUT_ + cglob) * PLANE + gy * HW_ + gx;
            float s0 = sigmoidf_(v0);
            float s1 = sigmoidf_(v1);
            if (gate == 0) {
                g_rh[idx]     = s0 * g_h[idx];
                g_rh[idx + 1] = s1 * g_h[idx + 1];
            } else {
                g_z[idx]     = s0;
                g_z[idx + 1] = s1;
            }
        }
    }
}

// grid: (3, 3, 32)  bz: b = bz>>3, cg = bz&7  (COB=8)
__global__ void __launch_bounds__(NTHR) update_kernel(
    const float* __restrict__ x,
    const float* __restrict__ w_h, const float* __restrict__ b_h,
    float* __restrict__ out, int t)
{
    const int bz = blockIdx.z;
    const int b  = bz >> 3;
    const int cg = bz & 7;

    const float* srcA = x + (size_t)(b * T_ + t) * CIN_ * PLANE;
    const float* srcB = g_rh + (size_t)b * COUT_ * PLANE;

    u64 acc[4][8];
    const int tid = threadIdx.x;
    conv_tile<8>(srcA, srcB, w_h, b_h, cg * 8, blockIdx.x, blockIdx.y, tid, acc);

    const int tx = tid & 15, ty = tid >> 4;
    const int gy0 = blockIdx.y * TILE + ty * 4;
    const int gx  = blockIdx.x * TILE + tx * 2;
    #pragma unroll
    for (int pr = 0; pr < 4; pr++) {
        int gy = gy0 + pr;
        #pragma unroll
        for (int co = 0; co < 8; co++) {
            float v0, v1; unpack2(acc[pr][co], v0, v1);
            int cglob = cg * 8 + co;
            size_t idx  = (size_t)(b * COUT_ + cglob) * PLANE + gy * HW_ + gx;
            size_t oidx = (size_t)((b * T_ + t) * COUT_ + cglob) * PLANE + gy * HW_ + gx;
            float ht0 = tanhf(v0), ht1 = tanhf(v1);
            float z0 = g_z[idx],     z1 = g_z[idx + 1];
            float h0 = g_h[idx],     h1 = g_h[idx + 1];
            float hn0 = h0 + z0 * (ht0 - h0);
            float hn1 = h1 + z1 * (ht1 - h1);
            g_h[idx]     = hn0;  g_h[idx + 1] = hn1;
            out[oidx]    = hn0;  out[oidx + 1] = hn1;
        }
    }
}

__global__ void zero_h_kernel() {
    int i = blockIdx.x * 256 + threadIdx.x;
    if (i < B_ * COUT_ * PLANE) g_h[i] = 0.0f;
}

extern "C" void kernel_launch(void* const* d_in, const int* in_sizes, int n_in,
                              void* d_out, int out_size)
{
    const float* x   = (const float*)d_in[0];
    const float* w_r = (const float*)d_in[1];
    const float* b_r = (const float*)d_in[2];
    const float* w_z = (const float*)d_in[3];
    const float* b_z = (const float*)d_in[4];
    const float* w_h = (const float*)d_in[5];
    const float* b_h = (const float*)d_in[6];
    float* out = (float*)d_out;

    static bool attr_done = false;
    const int smem_g = (int)sizeof(SM<16>);
    const int smem_u = (int)sizeof(SM<8>);
    if (!attr_done) {
        cudaFuncSetAttribute(gates_kernel,
            cudaFuncAttributeMaxDynamicSharedMemorySize, smem_g);
        cudaFuncSetAttribute(update_kernel,
            cudaFuncAttributeMaxDynamicSharedMemorySize, smem_u);
        attr_done = true;
    }

    zero_h_kernel<<<(B_ * COUT_ * PLANE + 255) / 256, 256>>>();

    dim3 gGrid(HW_ / TILE, HW_ / TILE, B_ * 2 * (COUT_ / 16));  // 3,3,32
    dim3 uGrid(HW_ / TILE, HW_ / TILE, B_ * (COUT_ / 8));       // 3,3,32
    for (int t = 0; t < T_; t++) {
        gates_kernel<<<gGrid, NTHR, smem_g>>>(x, w_r, b_r, w_z, b_z, t);
        update_kernel<<<uGrid, NTHR, smem_u>>>(x, w_h, b_h, out, t);
    }
}

// round 10
// speedup vs baseline: 2.4382x; 1.2146x over previous
#include <cuda_runtime.h>
#include <math.h>
#include <stdint.h>

#define HW_    96
#define CIN_   64
#define COUT_  64
#define B_     4
#define T_     8
#define BT_    (B_*T_)
#define PLANE  (HW_*HW_)
#define TILE   32
#define CICH   8
#define NCHUNK 8           // K=64 per phase
#define HALO   34
#define SPITCH 36
#define NTHR   256

// ---- persistent scratch (static device allocations only) ----
__device__ float g_h  [B_*COUT_*PLANE];
__device__ float g_rh [B_*COUT_*PLANE];
__device__ float g_z  [B_*COUT_*PLANE];
#define XSZ ((size_t)BT_*COUT_*PLANE)
__device__ float g_xacc[3*XSZ];        // conv-of-x (+bias) for r,z,h

typedef unsigned long long u64;

__device__ __forceinline__ u64 pack2(float lo, float hi) {
    u64 r; asm("mov.b64 %0, {%1, %2};" : "=l"(r) : "f"(lo), "f"(hi)); return r;
}
__device__ __forceinline__ void unpack2(u64 v, float &lo, float &hi) {
    asm("mov.b64 {%0, %1}, %2;" : "=f"(lo), "=f"(hi) : "l"(v));
}
__device__ __forceinline__ void fma2(u64 &d, u64 a, u64 b) {
    asm("fma.rn.f32x2 %0, %1, %2, %0;" : "+l"(d) : "l"(a), "l"(b));
}
__device__ __forceinline__ uint32_t s2u(const void* p) {
    return (uint32_t)__cvta_generic_to_shared(p);
}
__device__ __forceinline__ void cp4(uint32_t smem, const float* g, bool v) {
    asm volatile("cp.async.ca.shared.global [%0], [%1], 4, %2;"
                 :: "r"(smem), "l"(g), "r"(v ? 4u : 0u));
}
#define CP_COMMIT() asm volatile("cp.async.commit_group;" ::: "memory")
#define CP_WAIT0()  asm volatile("cp.async.wait_group 0;"  ::: "memory")

template<int WTOT> struct SMData {
    float in[2][CICH][HALO][SPITCH];
    u64   w [2][CICH][WTOT][10];
};

// ---------------------------------------------------------------------------
// K=64 conv over `src` (64ch image) for WTOT weight-slots.
// Thread layout: 256 thr; tx=tid&15 (x pair), ty=tid>>4 (2-row group).
// my_w: this thread's weight base (co & koff already folded), advances by chunk.
// acc[pr][slot] packed pixel pairs.
// ---------------------------------------------------------------------------
template<int WTOT>
__device__ __forceinline__ void conv64(
    const float* __restrict__ src,
    const float* __restrict__ my_w, bool wact, int wci,
    int tile_x, int tile_y, int tid,
    u64 acc[2][WTOT])
{
    extern __shared__ char dynsmem[];
    SMData<WTOT>* sm = reinterpret_cast<SMData<WTOT>*>(dynsmem);

    const int tx   = tid & 15;
    const int ty   = tid >> 4;
    const int wid  = tid >> 5;       // warp id = input channel within chunk
    const int lane = tid & 31;
    const int lx = tx * 2;
    const int ly = ty * 2;
    const int base_y = tile_y * TILE - 1;
    const int base_x = tile_x * TILE - 1;

    auto loadw = [&](int c, float wreg[9]) {
        const float* wp = my_w + (size_t)(c * CICH + wci) * 9;
        #pragma unroll
        for (int k = 0; k < 9; k++) wreg[k] = wp[k];
    };
    auto stsw = [&](int c, const float wreg[9]) {
        int buf = c & 1;
        int wslot = wact ? (tid >> 3) : 0;
        #pragma unroll
        for (int k = 0; k < 9; k++)
            sm->w[buf][wci][wslot][k] = pack2(wreg[k], wreg[k]);
    };
    auto cpin = [&](int c) {
        int buf = c & 1;
        const float* chp = src + (size_t)(c * CICH + wid) * PLANE;
        for (int r = 0; r < HALO; r++) {
            int gy = base_y + r;
            bool rok = (unsigned)gy < HW_;
            int gx0 = base_x + lane;
            cp4(s2u(&sm->in[buf][wid][r][lane]), chp + gy * HW_ + gx0,
                rok && (unsigned)gx0 < HW_);
            if (lane < 2) {
                int gx1 = gx0 + 32;
                cp4(s2u(&sm->in[buf][wid][r][lane + 32]), chp + gy * HW_ + gx1,
                    rok && (unsigned)gx1 < HW_);
            }
        }
    };

    float wreg[9];
    if (wact) loadw(0, wreg);
    cpin(0);
    CP_COMMIT();
    if (wact) stsw(0, wreg);

    for (int c = 0; c < NCHUNK; c++) {
        const int buf = c & 1;
        const bool more = (c + 1) < NCHUNK;
        if (more && wact) loadw(c + 1, wreg);
        CP_WAIT0();
        __syncthreads();
        if (more) {
            cpin(c + 1);
            CP_COMMIT();
            if (wact) stsw(c + 1, wreg);
        }
        #pragma unroll
        for (int ci = 0; ci < CICH; ci++) {
            const float* ip = &sm->in[buf][ci][ly][lx];
            u64 p[4][3];
            #pragma unroll
            for (int r = 0; r < 4; r++) {
                float2 q0 = *(const float2*)(ip + r * SPITCH);
                float2 q1 = *(const float2*)(ip + r * SPITCH + 2);
                p[r][0] = pack2(q0.x, q0.y);
                p[r][1] = pack2(q0.y, q1.x);
                p[r][2] = pack2(q1.x, q1.y);
            }
            const u64* wrow = &sm->w[buf][ci][0][0];
            #pragma unroll
            for (int s = 0; s < WTOT; s++) {
                // first half of kernel taps (k = 0..3)
                ulonglong2 t0 = *(const ulonglong2*)(wrow + s * 10 + 0);
                ulonglong2 t1 = *(const ulonglong2*)(wrow + s * 10 + 2);
                u64 wa[4] = {t0.x, t0.y, t1.x, t1.y};
                #pragma unroll
                for (int k = 0; k < 4; k++) {
                    int ky = k / 3, kx = k - ky * 3;
                    fma2(acc[0][s], wa[k], p[0 + ky][kx]);
                    fma2(acc[1][s], wa[k], p[1 + ky][kx]);
                }
                // second half (k = 4..8)
                ulonglong2 t2 = *(const ulonglong2*)(wrow + s * 10 + 4);
                ulonglong2 t3 = *(const ulonglong2*)(wrow + s * 10 + 6);
                u64 w8 = wrow[s * 10 + 8];
                u64 wb[5] = {t2.x, t2.y, t3.x, t3.y, w8};
                #pragma unroll
                for (int j = 0; j < 5; j++) {
                    int k = j + 4;
                    int ky = k / 3, kx = k - ky * 3;
                    fma2(acc[0][s], wb[j], p[0 + ky][kx]);
                    fma2(acc[1][s], wb[j], p[1 + ky][kx]);
                }
            }
        }
    }
}

__device__ __forceinline__ float sigmoidf_(float v) {
    return 1.0f / (1.0f + expf(-v));
}

// ===========================================================================
// Phase 1: precompute conv-of-x (+bias) for all (b,t) and all 3 convs.
// grid (3,3, 3*32*4): bz -> cog = bz&3, bt = (bz>>2)&31, conv = bz>>7
// ===========================================================================
__global__ void __launch_bounds__(NTHR, 2) xconv_kernel(
    const float* __restrict__ x,
    const float* __restrict__ w_r, const float* __restrict__ b_r,
    const float* __restrict__ w_z, const float* __restrict__ b_z,
    const float* __restrict__ w_h, const float* __restrict__ b_h)
{
    const int bz   = blockIdx.z;
    const int cog  = bz & 3;
    const int bt   = (bz >> 2) & 31;
    const int conv = bz >> 7;

    const float* wts  = (conv == 0) ? w_r : (conv == 1) ? w_z : w_h;
    const float* bias = (conv == 0) ? b_r : (conv == 1) ? b_z : b_h;
    const float* src  = x + (size_t)bt * CIN_ * PLANE;

    const int tid  = threadIdx.x;
    const int wci  = tid & 7;
    const int wslot = tid >> 3;
    const bool wact = (wslot < 16);
    const int my_co = cog * 16 + (wact ? wslot : 0);
    const float* my_w = wts + (size_t)my_co * (CIN_ + COUT_) * 9;   // koff = 0

    u64 acc[2][16];
    #pragma unroll
    for (int s = 0; s < 16; s++) {
        float bv = bias[cog * 16 + s];
        acc[0][s] = pack2(bv, bv);
        acc[1][s] = acc[0][s];
    }

    conv64<16>(src, my_w, wact, wci, blockIdx.x, blockIdx.y, tid, acc);

    const int tx = tid & 15, ty = tid >> 4;
    const int gy0 = blockIdx.y * TILE + ty * 2;
    const int gx  = blockIdx.x * TILE + tx * 2;
    float* dst = g_xacc + (size_t)conv * XSZ;
    #pragma unroll
    for (int pr = 0; pr < 2; pr++) {
        int gy = gy0 + pr;
        #pragma unroll
        for (int s = 0; s < 16; s++) {
            int co = cog * 16 + s;
            float v0, v1; unpack2(acc[pr][s], v0, v1);
            *(float2*)(dst + ((size_t)(bt * COUT_ + co)) * PLANE + gy * HW_ + gx)
                = make_float2(v0, v1);
        }
    }
}

// ===========================================================================
// Phase 2a: gates. Computes r AND z (8 channels each) from one h-tile fill.
// grid (3,3, 4*8): bz -> cog = bz&7, b = bz>>3
// ===========================================================================
__global__ void __launch_bounds__(NTHR, 2) gates_kernel(
    const float* __restrict__ w_r,
    const float* __restrict__ w_z,
    int t)
{
    const int bz  = blockIdx.z;
    const int cog = bz & 7;
    const int b   = bz >> 3;
    const int bt  = b * T_ + t;

    const float* src = g_h + (size_t)b * COUT_ * PLANE;

    const int tid   = threadIdx.x;
    const int wci   = tid & 7;
    const int wslot = tid >> 3;           // 0..31; active if < 16
    const bool wact = (wslot < 16);
    const int sconv = wact ? (wslot >> 3) : 0;        // 0=r, 1=z
    const int my_co = cog * 8 + (wact ? (wslot & 7) : 0);
    const float* wb = sconv ? w_z : w_r;
    const float* my_w = wb + ((size_t)my_co * (CIN_ + COUT_) + CIN_) * 9;  // h-part

    const int tx = tid & 15, ty = tid >> 4;
    const int gy0 = blockIdx.y * TILE + ty * 2;
    const int gx  = blockIdx.x * TILE + tx * 2;

    // init acc from precomputed x-conv (+bias)
    u64 acc[2][16];
    #pragma unroll
    for (int pr = 0; pr < 2; pr++) {
        int gy = gy0 + pr;
        #pragma unroll
        for (int s = 0; s < 16; s++) {
            int conv = s >> 3;                        // 0=r, 1=z
            int co = cog * 8 + (s & 7);
            float2 q = *(const float2*)(g_xacc + (size_t)conv * XSZ +
                ((size_t)(bt * COUT_ + co)) * PLANE + gy * HW_ + gx);
            acc[pr][s] = pack2(q.x, q.y);
        }
    }

    conv64<16>(src, my_w, wact, wci, blockIdx.x, blockIdx.y, tid, acc);

    #pragma unroll
    for (int pr = 0; pr < 2; pr++) {
        int gy = gy0 + pr;
        #pragma unroll
        for (int s = 0; s < 8; s++) {
            int co = cog * 8 + s;
            size_t idx = (size_t)(b * COUT_ + co) * PLANE + gy * HW_ + gx;
            float r0, r1, z0, z1;
            unpack2(acc[pr][s], r0, r1);
            unpack2(acc[pr][s + 8], z0, z1);
            float h0 = g_h[idx], h1 = g_h[idx + 1];
            g_rh[idx]     = sigmoidf_(r0) * h0;
            g_rh[idx + 1] = sigmoidf_(r1) * h1;
            g_z[idx]      = sigmoidf_(z0);
            g_z[idx + 1]  = sigmoidf_(z1);
        }
    }
}

// ===========================================================================
// Phase 2b: update. h-tilde conv over r*h, then GRU update.
// grid (3,3, 4*8): bz -> cog = bz&7, b = bz>>3
// ===========================================================================
__global__ void __launch_bounds__(NTHR, 2) update_kernel(
    const float* __restrict__ w_h,
    float* __restrict__ out, int t)
{
    const int bz  = blockIdx.z;
    const int cog = bz & 7;
    const int b   = bz >> 3;
    const int bt  = b * T_ + t;

    const float* src = g_rh + (size_t)b * COUT_ * PLANE;

    const int tid   = threadIdx.x;
    const int wci   = tid & 7;
    const int wslot = tid >> 3;           // active if < 8
    const bool wact = (wslot < 8);
    const int my_co = cog * 8 + (wact ? wslot : 0);
    const float* my_w = w_h + ((size_t)my_co * (CIN_ + COUT_) + CIN_) * 9;

    const int tx = tid & 15, ty = tid >> 4;
    const int gy0 = blockIdx.y * TILE + ty * 2;
    const int gx  = blockIdx.x * TILE + tx * 2;

    u64 acc[2][8];
    #pragma unroll
    for (int pr = 0; pr < 2; pr++) {
        int gy = gy0 + pr;
        #pragma unroll
        for (int s = 0; s < 8; s++) {
            int co = cog * 8 + s;
            float2 q = *(const float2*)(g_xacc + 2 * XSZ +
                ((size_t)(bt * COUT_ + co)) * PLANE + gy * HW_ + gx);
            acc[pr][s] = pack2(q.x, q.y);
        }
    }

    conv64<8>(src, my_w, wact, wci, blockIdx.x, blockIdx.y, tid, acc);

    #pragma unroll
    for (int pr = 0; pr < 2; pr++) {
        int gy = gy0 + pr;
        #pragma unroll
        for (int s = 0; s < 8; s++) {
            int co = cog * 8 + s;
            size_t idx  = (size_t)(b * COUT_ + co) * PLANE + gy * HW_ + gx;
            size_t oidx = (size_t)(bt * COUT_ + co) * PLANE + gy * HW_ + gx;
            float v0, v1; unpack2(acc[pr][s], v0, v1);
            float ht0 = tanhf(v0), ht1 = tanhf(v1);
            float z0 = g_z[idx],  z1 = g_z[idx + 1];
            float h0 = g_h[idx],  h1 = g_h[idx + 1];
            float hn0 = h0 + z0 * (ht0 - h0);
            float hn1 = h1 + z1 * (ht1 - h1);
            g_h[idx]     = hn0;  g_h[idx + 1] = hn1;
            out[oidx]    = hn0;  out[oidx + 1] = hn1;
        }
    }
}

__global__ void zero_h_kernel() {
    int i = blockIdx.x * 256 + threadIdx.x;
    if (i < B_ * COUT_ * PLANE) g_h[i] = 0.0f;
}

extern "C" void kernel_launch(void* const* d_in, const int* in_sizes, int n_in,
                              void* d_out, int out_size)
{
    const float* x   = (const float*)d_in[0];
    const float* w_r = (const float*)d_in[1];
    const float* b_r = (const float*)d_in[2];
    const float* w_z = (const float*)d_in[3];
    const float* b_z = (const float*)d_in[4];
    const float* w_h = (const float*)d_in[5];
    const float* b_h = (const float*)d_in[6];
    float* out = (float*)d_out;

    static bool attr_done = false;
    const int smem16 = (int)sizeof(SMData<16>);
    const int smem8  = (int)sizeof(SMData<8>);
    if (!attr_done) {
        cudaFuncSetAttribute(xconv_kernel,
            cudaFuncAttributeMaxDynamicSharedMemorySize, smem16);
        cudaFuncSetAttribute(gates_kernel,
            cudaFuncAttributeMaxDynamicSharedMemorySize, smem16);
        cudaFuncSetAttribute(update_kernel,
            cudaFuncAttributeMaxDynamicSharedMemorySize, smem8);
        attr_done = true;
    }

    zero_h_kernel<<<(B_ * COUT_ * PLANE + 255) / 256, 256>>>();

    dim3 xGrid(3, 3, 3 * BT_ * 4);       // 3456 blocks, fully parallel
    xconv_kernel<<<xGrid, NTHR, smem16>>>(x, w_r, b_r, w_z, b_z, w_h, b_h);

    dim3 sGrid(3, 3, B_ * 8);            // 288 blocks
    for (int t = 0; t < T_; t++) {
        gates_kernel<<<sGrid, NTHR, smem16>>>(w_r, w_z, t);
        update_kernel<<<sGrid, NTHR, smem8>>>(w_h, out, t);
    }
}

// round 12
// speedup vs baseline: 2.5172x; 1.0324x over previous
#include <cuda_runtime.h>
#include <math.h>
#include <stdint.h>

#define HW_    96
#define CIN_   64
#define COUT_  64
#define B_     4
#define T_     8
#define BT_    (B_*T_)
#define PLANE  (HW_*HW_)
#define TILE   32
#define CICH   8
#define NCHUNK 8           // K=64 per phase
#define HALO   34
#define SPITCH 36
#define INPLN  (4 + HALO*SPITCH)   // per-channel padded plane (floats)
#define NTHR   256

// ---- persistent scratch (static device allocations only) ----
__device__ float g_h  [B_*COUT_*PLANE];
__device__ float g_rh [B_*COUT_*PLANE];
__device__ float g_z  [B_*COUT_*PLANE];
#define XSZ ((size_t)BT_*COUT_*PLANE)
__device__ float g_xacc[3*XSZ];        // conv-of-x (+bias) for r,z,h

typedef unsigned long long u64;

__device__ __forceinline__ u64 pack2(float lo, float hi) {
    u64 r; asm("mov.b64 %0, {%1, %2};" : "=l"(r) : "f"(lo), "f"(hi)); return r;
}
__device__ __forceinline__ void unpack2(u64 v, float &lo, float &hi) {
    asm("mov.b64 {%0, %1}, %2;" : "=f"(lo), "=f"(hi) : "l"(v));
}
__device__ __forceinline__ void fma2(u64 &d, u64 a, u64 b) {
    asm("fma.rn.f32x2 %0, %1, %2, %0;" : "+l"(d) : "l"(a), "l"(b));
}
__device__ __forceinline__ uint32_t s2u(const void* p) {
    return (uint32_t)__cvta_generic_to_shared(p);
}
__device__ __forceinline__ void cp4(uint32_t smem, const float* g, bool v) {
    asm volatile("cp.async.ca.shared.global [%0], [%1], 4, %2;"
                 :: "r"(smem), "l"(g), "r"(v ? 4u : 0u));
}
__device__ __forceinline__ void cp16(uint32_t smem, const float* g, bool v) {
    asm volatile("cp.async.cg.shared.global [%0], [%1], 16, %2;"
                 :: "r"(smem), "l"(g), "r"(v ? 16u : 0u));
}
#define CP_COMMIT() asm volatile("cp.async.commit_group;" ::: "memory")
#define CP_WAIT0()  asm volatile("cp.async.wait_group 0;"  ::: "memory")

template<int WTOT> struct SMData {
    float in[2][CICH][INPLN];          // per channel: pad(4) + 34 rows of 36
    u64   w [2][CICH][WTOT][10];
};

// ---------------------------------------------------------------------------
// K=64 conv over `src` (64ch image) for WTOT weight-slots.
// 256 thr: tx=tid&15 (x pair), ty=tid>>4 (2-row group). Warp wid = channel.
// smem channel plane layout (floats, data base d = plane+4, 16B aligned):
//   d[r*36 + 0..31]  = gmem x in [tx32, tx32+32)   (cp16 x8, always valid)
//   d[r*36 + 32]     = right halo (gmem x = tx32+32)
//   d[r*36 - 1]      = left  halo (gmem x = tx32-1)  [prev row's tail slot]
// ---------------------------------------------------------------------------
template<int WTOT>
__device__ __forceinline__ void conv64(
    const float* __restrict__ src,
    const float* __restrict__ my_w, bool wact, int wci,
    int tile_x, int tile_y, int tid,
    u64 acc[2][WTOT])
{
    extern __shared__ char dynsmem[];
    SMData<WTOT>* sm = reinterpret_cast<SMData<WTOT>*>(dynsmem);

    const int tx   = tid & 15;
    const int ty   = tid >> 4;
    const int wid  = tid >> 5;       // warp id = input channel within chunk
    const int lane = tid & 31;
    const int lx = tx * 2;
    const int ly = ty * 2;
    const int base_y = tile_y * TILE - 1;
    const int base_x = tile_x * TILE - 1;     // left halo gmem x
    const int main_x = base_x + 1;            // 16B-aligned gmem column

    auto loadw = [&](int c, float wreg[9]) {
        const float* wp = my_w + (size_t)(c * CICH + wci) * 9;
        #pragma unroll
        for (int k = 0; k < 9; k++) wreg[k] = wp[k];
    };
    auto stsw = [&](int c, const float wreg[9]) {
        int buf = c & 1;
        int wslot = wact ? (tid >> 3) : 0;
        #pragma unroll
        for (int k = 0; k < 9; k++)
            sm->w[buf][wci][wslot][k] = pack2(wreg[k], wreg[k]);
    };
    auto cpin = [&](int c) {
        int buf = c & 1;
        const float* chp = src + (size_t)(c * CICH + wid) * PLANE;
        float* sbase = &sm->in[buf][wid][4];
        // mains: 34 rows x 8 segs of 16B = 272 ops across 32 lanes
        #pragma unroll
        for (int it = 0; it < 9; it++) {
            int idx = it * 32 + lane;
            if (idx < 272) {
                int r = idx >> 3, seg = idx & 7;
                int gy = base_y + r;
                bool ok = (unsigned)gy < HW_;
                cp16(s2u(sbase + r * SPITCH + seg * 4),
                     chp + gy * HW_ + main_x + seg * 4, ok);
            }
        }
        // edges: 34 rows x {left, right} = 68 ops
        #pragma unroll
        for (int it = 0; it < 3; it++) {
            int idx = it * 32 + lane;
            if (idx < 68) {
                int r = idx >> 1, side = idx & 1;
                int gy = base_y + r;
                int gx = side ? (base_x + 33) : base_x;
                bool ok = ((unsigned)gy < HW_) && ((unsigned)gx < HW_);
                cp4(s2u(sbase + r * SPITCH + (side ? 32 : -1)),
                    chp + gy * HW_ + gx, ok);
            }
        }
    };

    float wreg[9];
    if (wact) loadw(0, wreg);
    cpin(0);
    CP_COMMIT();
    if (wact) stsw(0, wreg);

    for (int c = 0; c < NCHUNK; c++) {
        const int buf = c & 1;
        const bool more = (c + 1) < NCHUNK;
        if (more && wact) loadw(c + 1, wreg);
        CP_WAIT0();
        __syncthreads();
        if (more) {
            cpin(c + 1);
            CP_COMMIT();
            if (wact) stsw(c + 1, wreg);
        }
        #pragma unroll
        for (int ci = 0; ci < CICH; ci++) {
            const float* dp = &sm->in[buf][ci][4] + ly * SPITCH + lx;
            u64 p[4][3];
            #pragma unroll
            for (int r = 0; r < 4; r++) {
                float  sl = dp[r * SPITCH - 1];
                float2 q0 = *(const float2*)(dp + r * SPITCH);
                float  sr = dp[r * SPITCH + 2];
                p[r][0] = pack2(sl, q0.x);
                p[r][1] = pack2(q0.x, q0.y);
                p[r][2] = pack2(q0.y, sr);
            }
            const u64* wrow = &sm->w[buf][ci][0][0];
            #pragma unroll
            for (int s = 0; s < WTOT; s++) {
                ulonglong2 t0 = *(const ulonglong2*)(wrow + s * 10 + 0);
                ulonglong2 t1 = *(const ulonglong2*)(wrow + s * 10 + 2);
                u64 wa[4] = {t0.x, t0.y, t1.x, t1.y};
                #pragma unroll
                for (int k = 0; k < 4; k++) {
                    int ky = k / 3, kx = k - ky * 3;
                    fma2(acc[0][s], wa[k], p[0 + ky][kx]);
                    fma2(acc[1][s], wa[k], p[1 + ky][kx]);
                }
                ulonglong2 t2 = *(const ulonglong2*)(wrow + s * 10 + 4);
                ulonglong2 t3 = *(const ulonglong2*)(wrow + s * 10 + 6);
                u64 w8 = wrow[s * 10 + 8];
                u64 wb[5] = {t2.x, t2.y, t3.x, t3.y, w8};
                #pragma unroll
                for (int j = 0; j < 5; j++) {
                    int k = j + 4;
                    int ky = k / 3, kx = k - ky * 3;
                    fma2(acc[0][s], wb[j], p[0 + ky][kx]);
                    fma2(acc[1][s], wb[j], p[1 + ky][kx]);
                }
            }
        }
    }
}

__device__ __forceinline__ float sigmoidf_(float v) {
    return 1.0f / (1.0f + expf(-v));
}

// ===========================================================================
// Phase 1: precompute conv-of-x (+bias) for all (b,t) and all 3 convs.
// grid (3,3, 3*32*4): bz -> cog = bz&3, bt = (bz>>2)&31, conv = bz>>7
// ===========================================================================
__global__ void __launch_bounds__(NTHR, 2) xconv_kernel(
    const float* __restrict__ x,
    const float* __restrict__ w_r, const float* __restrict__ b_r,
    const float* __restrict__ w_z, const float* __restrict__ b_z,
    const float* __restrict__ w_h, const float* __restrict__ b_h)
{
    const int bz   = blockIdx.z;
    const int cog  = bz & 3;
    const int bt   = (bz >> 2) & 31;
    const int conv = bz >> 7;

    const float* wts  = (conv == 0) ? w_r : (conv == 1) ? w_z : w_h;
    const float* bias = (conv == 0) ? b_r : (conv == 1) ? b_z : b_h;
    const float* src  = x + (size_t)bt * CIN_ * PLANE;

    const int tid  = threadIdx.x;
    const int wci  = tid & 7;
    const int wslot = tid >> 3;
    const bool wact = (wslot < 16);
    const int my_co = cog * 16 + (wact ? wslot : 0);
    const float* my_w = wts + (size_t)my_co * (CIN_ + COUT_) * 9;   // koff = 0

    u64 acc[2][16];
    #pragma unroll
    for (int s = 0; s < 16; s++) {
        float bv = bias[cog * 16 + s];
        acc[0][s] = pack2(bv, bv);
        acc[1][s] = acc[0][s];
    }

    conv64<16>(src, my_w, wact, wci, blockIdx.x, blockIdx.y, tid, acc);

    const int tx = tid & 15, ty = tid >> 4;
    const int gy0 = blockIdx.y * TILE + ty * 2;
    const int gx  = blockIdx.x * TILE + tx * 2;
    float* dst = g_xacc + (size_t)conv * XSZ;
    #pragma unroll
    for (int pr = 0; pr < 2; pr++) {
        int gy = gy0 + pr;
        #pragma unroll
        for (int s = 0; s < 16; s++) {
            int co = cog * 16 + s;
            float v0, v1; unpack2(acc[pr][s], v0, v1);
            *(float2*)(dst + ((size_t)(bt * COUT_ + co)) * PLANE + gy * HW_ + gx)
                = make_float2(v0, v1);
        }
    }
}

// ===========================================================================
// Phase 2a: gates. Computes r AND z (8 channels each) from one h-tile fill.
// grid (3,3, 4*8): bz -> cog = bz&7, b = bz>>3
// ===========================================================================
__global__ void __launch_bounds__(NTHR, 2) gates_kernel(
    const float* __restrict__ w_r,
    const float* __restrict__ w_z,
    int t)
{
    const int bz  = blockIdx.z;
    const int cog = bz & 7;
    const int b   = bz >> 3;
    const int bt  = b * T_ + t;

    const float* src = g_h + (size_t)b * COUT_ * PLANE;

    const int tid   = threadIdx.x;
    const int wci   = tid & 7;
    const int wslot = tid >> 3;           // 0..31; active if < 16
    const bool wact = (wslot < 16);
    const int sconv = wact ? (wslot >> 3) : 0;        // 0=r, 1=z
    const int my_co = cog * 8 + (wact ? (wslot & 7) : 0);
    const float* wb = sconv ? w_z : w_r;
    const float* my_w = wb + ((size_t)my_co * (CIN_ + COUT_) + CIN_) * 9;  // h-part

    const int tx = tid & 15, ty = tid >> 4;
    const int gy0 = blockIdx.y * TILE + ty * 2;
    const int gx  = blockIdx.x * TILE + tx * 2;

    // init acc from precomputed x-conv (+bias)
    u64 acc[2][16];
    #pragma unroll
    for (int pr = 0; pr < 2; pr++) {
        int gy = gy0 + pr;
        #pragma unroll
        for (int s = 0; s < 16; s++) {
            int conv = s >> 3;                        // 0=r, 1=z
            int co = cog * 8 + (s & 7);
            float2 q = *(const float2*)(g_xacc + (size_t)conv * XSZ +
                ((size_t)(bt * COUT_ + co)) * PLANE + gy * HW_ + gx);
            acc[pr][s] = pack2(q.x, q.y);
        }
    }

    conv64<16>(src, my_w, wact, wci, blockIdx.x, blockIdx.y, tid, acc);

    #pragma unroll
    for (int pr = 0; pr < 2; pr++) {
        int gy = gy0 + pr;
        #pragma unroll
        for (int s = 0; s < 8; s++) {
            int co = cog * 8 + s;
            size_t idx = (size_t)(b * COUT_ + co) * PLANE + gy * HW_ + gx;
            float r0, r1, z0, z1;
            unpack2(acc[pr][s], r0, r1);
            unpack2(acc[pr][s + 8], z0, z1);
            float h0 = g_h[idx], h1 = g_h[idx + 1];
            g_rh[idx]     = sigmoidf_(r0) * h0;
            g_rh[idx + 1] = sigmoidf_(r1) * h1;
            g_z[idx]      = sigmoidf_(z0);
            g_z[idx + 1]  = sigmoidf_(z1);
        }
    }
}

// ===========================================================================
// Phase 2b: update. h-tilde conv over r*h, then GRU update.
// grid (3,3, 4*8): bz -> cog = bz&7, b = bz>>3
// ===========================================================================
__global__ void __launch_bounds__(NTHR, 2) update_kernel(
    const float* __restrict__ w_h,
    float* __restrict__ out, int t)
{
    const int bz  = blockIdx.z;
    const int cog = bz & 7;
    const int b   = bz >> 3;
    const int bt  = b * T_ + t;

    const float* src = g_rh + (size_t)b * COUT_ * PLANE;

    const int tid   = threadIdx.x;
    const int wci   = tid & 7;
    const int wslot = tid >> 3;           // active if < 8
    const bool wact = (wslot < 8);
    const int my_co = cog * 8 + (wact ? wslot : 0);
    const float* my_w = w_h + ((size_t)my_co * (CIN_ + COUT_) + CIN_) * 9;

    const int tx = tid & 15, ty = tid >> 4;
    const int gy0 = blockIdx.y * TILE + ty * 2;
    const int gx  = blockIdx.x * TILE + tx * 2;

    u64 acc[2][8];
    #pragma unroll
    for (int pr = 0; pr < 2; pr++) {
        int gy = gy0 + pr;
        #pragma unroll
        for (int s = 0; s < 8; s++) {
            int co = cog * 8 + s;
            float2 q = *(const float2*)(g_xacc + 2 * XSZ +
                ((size_t)(bt * COUT_ + co)) * PLANE + gy * HW_ + gx);
            acc[pr][s] = pack2(q.x, q.y);
        }
    }

    conv64<8>(src, my_w, wact, wci, blockIdx.x, blockIdx.y, tid, acc);

    #pragma unroll
    for (int pr = 0; pr < 2; pr++) {
        int gy = gy0 + pr;
        #pragma unroll
        for (int s = 0; s < 8; s++) {
            int co = cog * 8 + s;
            size_t idx  = (size_t)(b * COUT_ + co) * PLANE + gy * HW_ + gx;
            size_t oidx = (size_t)(bt * COUT_ + co) * PLANE + gy * HW_ + gx;
            float v0, v1; unpack2(acc[pr][s], v0, v1);
            float ht0 = tanhf(v0), ht1 = tanhf(v1);
            float z0 = g_z[idx],  z1 = g_z[idx + 1];
            float h0 = g_h[idx],  h1 = g_h[idx + 1];
            float hn0 = h0 + z0 * (ht0 - h0);
            float hn1 = h1 + z1 * (ht1 - h1);
            g_h[idx]     = hn0;  g_h[idx + 1] = hn1;
            out[oidx]    = hn0;  out[oidx + 1] = hn1;
        }
    }
}

__global__ void zero_h_kernel() {
    int i = blockIdx.x * 256 + threadIdx.x;
    if (i < B_ * COUT_ * PLANE) g_h[i] = 0.0f;
}

extern "C" void kernel_launch(void* const* d_in, const int* in_sizes, int n_in,
                              void* d_out, int out_size)
{
    const float* x   = (const float*)d_in[0];
    const float* w_r = (const float*)d_in[1];
    const float* b_r = (const float*)d_in[2];
    const float* w_z = (const float*)d_in[3];
    const float* b_z = (const float*)d_in[4];
    const float* w_h = (const float*)d_in[5];
    const float* b_h = (const float*)d_in[6];
    float* out = (float*)d_out;

    static bool attr_done = false;
    const int smem16 = (int)sizeof(SMData<16>);
    const int smem8  = (int)sizeof(SMData<8>);
    if (!attr_done) {
        cudaFuncSetAttribute(xconv_kernel,
            cudaFuncAttributeMaxDynamicSharedMemorySize, smem16);
        cudaFuncSetAttribute(gates_kernel,
            cudaFuncAttributeMaxDynamicSharedMemorySize, smem16);
        cudaFuncSetAttribute(update_kernel,
            cudaFuncAttributeMaxDynamicSharedMemorySize, smem8);
        attr_done = true;
    }

    zero_h_kernel<<<(B_ * COUT_ * PLANE + 255) / 256, 256>>>();

    dim3 xGrid(3, 3, 3 * BT_ * 4);       // 3456 blocks, fully parallel
    xconv_kernel<<<xGrid, NTHR, smem16>>>(x, w_r, b_r, w_z, b_z, w_h, b_h);

    dim3 sGrid(3, 3, B_ * 8);            // 288 blocks
    for (int t = 0; t < T_; t++) {
        gates_kernel<<<sGrid, NTHR, smem16>>>(w_r, w_z, t);
        update_kernel<<<sGrid, NTHR, smem8>>>(w_h, out, t);
    }
}